// round 5
// baseline (speedup 1.0000x reference)
#include <cuda_runtime.h>

// BinsCombinerLayer: out[b] = (1/NUM_BINS) * sum_{n,s} inputs[b,n,s] * centroids[n,s]
// B=32768, NUM_BINS=16, BIN_SIZE=128. Pure HBM/LTS-bound (268 MB stream-once).
//
// Evidence through R4: DRAM% saturates at ~81% (= ~6300 B/cyc LTS chip cap,
// path-independent) once >~50 warps/SM are resident; per-warp MLP is not a
// lever. This round removes the only remaining inefficiency: tail imbalance.
// 1024 blocks x 8 warps = 8192 warps -> exactly 4 examples per warp.

#define B_TOTAL       32768
#define ROW_FLOATS    2048               // NUM_BINS * BIN_SIZE
#define ROW_VEC4      (ROW_FLOATS / 4)   // 512 float4 per row
#define VEC_PER_LANE  (ROW_VEC4 / 32)    // 16 float4 per lane per example
#define THREADS       256
#define WARPS_PER_BLOCK (THREADS / 32)
#define GRID_BLOCKS   1024               // 8192 warps: 32768/8192 = 4 exactly
#define NWARPS        (GRID_BLOCKS * WARPS_PER_BLOCK)
#define ROUNDS        (B_TOTAL / NWARPS) // 4, no remainder
#define BLOCKS_PER_SM 8                  // reg budget 32 (R3-proven config)
#define INV_NUM_BINS  (1.0f / 16.0f)

__global__ __launch_bounds__(THREADS, BLOCKS_PER_SM)
void bins_combiner_kernel(const float* __restrict__ inputs,
                          const float* __restrict__ centroids,
                          float* __restrict__ out)
{
    __shared__ float4 sc[ROW_VEC4];   // 8 KB centroid table, block-resident

    const float4* c4 = reinterpret_cast<const float4*>(centroids);
    for (int i = threadIdx.x; i < ROW_VEC4; i += THREADS) {
        sc[i] = c4[i];
    }
    __syncthreads();

    const int warp  = threadIdx.x >> 5;
    const int lane  = threadIdx.x & 31;
    const int gwarp = blockIdx.x * WARPS_PER_BLOCK + warp;

    // Exactly ROUNDS=4 examples per warp; within a round the 8192 warps cover
    // a contiguous 64 MB span of the input (good chip-wide locality).
    #pragma unroll
    for (int r = 0; r < ROUNDS; ++r) {
        const int b = gwarp + r * NWARPS;
        const float4* __restrict__ row =
            reinterpret_cast<const float4*>(inputs + (size_t)b * ROW_FLOATS);

        float acc = 0.0f;
        #pragma unroll
        for (int k = 0; k < VEC_PER_LANE; ++k) {
            const int idx = lane + 32 * k;
            float4 v = __ldcs(&row[idx]);   // evict-first: stream-once data
            float4 c = sc[idx];             // conflict-free LDS.128
            acc += v.x * c.x;
            acc += v.y * c.y;
            acc += v.z * c.z;
            acc += v.w * c.w;
        }

        // Warp butterfly reduce
        #pragma unroll
        for (int off = 16; off > 0; off >>= 1) {
            acc += __shfl_xor_sync(0xFFFFFFFFu, acc, off);
        }

        if (lane == 0) {
            out[b] = acc * INV_NUM_BINS;
        }
    }
}

extern "C" void kernel_launch(void* const* d_in, const int* in_sizes, int n_in,
                              void* d_out, int out_size)
{
    const float* inputs    = (const float*)d_in[0];   // [32768, 16, 128] f32
    const float* centroids = (const float*)d_in[1];   // [16, 128] f32
    float* out             = (float*)d_out;           // [32768] f32

    bins_combiner_kernel<<<GRID_BLOCKS, THREADS>>>(inputs, centroids, out);
}

// round 6
// speedup vs baseline: 1.1396x; 1.1396x over previous
#include <cuda_runtime.h>

// BinsCombinerLayer: out[b] = (1/NUM_BINS) * sum_{n,s} inputs[b,n,s] * centroids[n,s]
// B=32768, NUM_BINS=16, BIN_SIZE=128. Pure HBM/LTS-bound (268 MB stream-once).
//
// Final configuration (empirical optimum across R1-R5):
//  - 1184 persistent blocks = exactly 8/SM on 148 SMs, 256 thr, regs capped 32
//    -> ~57 warps/SM resident, DRAM pipe fully fed (81% / 6.44 TB/s = LTS cap).
//  - grid-stride over examples: natural warp de-phasing keeps request arrival
//    smooth (R5 showed lockstep unrolled rounds collapse DRAM util to 69%).
//  - centroids in smem (R2 showed register-caching them costs 64 regs -> occ 24%).
//  - __ldcs streaming loads: input has zero reuse.
// Floor = 268.4 MB / 6.44 TB/s ~= 41.7 us kernel; this config measures 42.3 us.

#define B_TOTAL       32768
#define ROW_FLOATS    2048               // NUM_BINS * BIN_SIZE
#define ROW_VEC4      (ROW_FLOATS / 4)   // 512 float4 per row
#define VEC_PER_LANE  (ROW_VEC4 / 32)    // 16 float4 per lane per example
#define THREADS       256
#define WARPS_PER_BLOCK (THREADS / 32)
#define BLOCKS_PER_SM 8
#define GRID_BLOCKS   (148 * BLOCKS_PER_SM)   // 1184 persistent blocks
#define INV_NUM_BINS  (1.0f / 16.0f)

__global__ __launch_bounds__(THREADS, BLOCKS_PER_SM)
void bins_combiner_kernel(const float* __restrict__ inputs,
                          const float* __restrict__ centroids,
                          float* __restrict__ out)
{
    __shared__ float4 sc[ROW_VEC4];   // 8 KB centroid table, block-resident

    // Cooperative centroid stage (coalesced float4), once per persistent block
    const float4* c4 = reinterpret_cast<const float4*>(centroids);
    for (int i = threadIdx.x; i < ROW_VEC4; i += THREADS) {
        sc[i] = c4[i];
    }
    __syncthreads();

    const int warp   = threadIdx.x >> 5;
    const int lane   = threadIdx.x & 31;
    const int gwarp  = blockIdx.x * WARPS_PER_BLOCK + warp;
    const int nwarps = GRID_BLOCKS * WARPS_PER_BLOCK;   // 9472 warps

    // Grid-stride over examples (~3.46 per warp); warps de-phase naturally.
    for (int b = gwarp; b < B_TOTAL; b += nwarps) {
        const float4* __restrict__ row =
            reinterpret_cast<const float4*>(inputs + (size_t)b * ROW_FLOATS);

        float acc = 0.0f;
        #pragma unroll
        for (int k = 0; k < VEC_PER_LANE; ++k) {
            const int idx = lane + 32 * k;
            float4 v = __ldcs(&row[idx]);   // evict-first: stream-once data
            float4 c = sc[idx];             // conflict-free LDS.128
            acc += v.x * c.x;
            acc += v.y * c.y;
            acc += v.z * c.z;
            acc += v.w * c.w;
        }

        // Warp butterfly reduce
        #pragma unroll
        for (int off = 16; off > 0; off >>= 1) {
            acc += __shfl_xor_sync(0xFFFFFFFFu, acc, off);
        }

        if (lane == 0) {
            out[b] = acc * INV_NUM_BINS;
        }
    }
}

extern "C" void kernel_launch(void* const* d_in, const int* in_sizes, int n_in,
                              void* d_out, int out_size)
{
    const float* inputs    = (const float*)d_in[0];   // [32768, 16, 128] f32
    const float* centroids = (const float*)d_in[1];   // [16, 128] f32
    float* out             = (float*)d_out;           // [32768] f32

    bins_combiner_kernel<<<GRID_BLOCKS, THREADS>>>(inputs, centroids, out);
}

// round 7
// speedup vs baseline: 1.1463x; 1.0059x over previous
#include <cuda_runtime.h>

// BinsCombinerLayer: out[b] = (1/NUM_BINS) * sum_{n,s} inputs[b,n,s] * centroids[n,s]
// B=32768, NUM_BINS=16, BIN_SIZE=128. Pure HBM/LTS-bound (268 MB stream-once).
//
// Established across R1-R6: DRAM throughput for this pattern ceilings at
// ~6.3-6.4 TB/s with >=43 resident warps/SM and naturally de-phased
// grid-stride issue; per-warp MLP depth and tail shaping are non-levers
// (R2/R4/R5 all regressed). This round keeps the proven inner loop and
// warp layout but halves the block count (512 thr x 592 blocks = same
// 64 warps/SM, reg cap still 32) to halve centroid-staging L2 traffic
// (9.25 MB -> 4.6 MB) and block launch/sync overhead.

#define B_TOTAL       32768
#define ROW_FLOATS    2048               // NUM_BINS * BIN_SIZE
#define ROW_VEC4      (ROW_FLOATS / 4)   // 512 float4 per row
#define VEC_PER_LANE  (ROW_VEC4 / 32)    // 16 float4 per lane per example
#define THREADS       512
#define WARPS_PER_BLOCK (THREADS / 32)   // 16
#define BLOCKS_PER_SM 4                  // reg budget 65536/(512*4) = 32
#define GRID_BLOCKS   (148 * BLOCKS_PER_SM)   // 592 persistent blocks
#define INV_NUM_BINS  (1.0f / 16.0f)

__global__ __launch_bounds__(THREADS, BLOCKS_PER_SM)
void bins_combiner_kernel(const float* __restrict__ inputs,
                          const float* __restrict__ centroids,
                          float* __restrict__ out)
{
    __shared__ float4 sc[ROW_VEC4];   // 8 KB centroid table, block-resident

    // Cooperative centroid stage (coalesced float4), once per persistent block
    const float4* c4 = reinterpret_cast<const float4*>(centroids);
    for (int i = threadIdx.x; i < ROW_VEC4; i += THREADS) {
        sc[i] = c4[i];
    }
    __syncthreads();

    const int warp   = threadIdx.x >> 5;
    const int lane   = threadIdx.x & 31;
    const int gwarp  = blockIdx.x * WARPS_PER_BLOCK + warp;
    const int nwarps = GRID_BLOCKS * WARPS_PER_BLOCK;   // 9472 warps

    // Grid-stride over examples (~3.46 per warp); warps de-phase naturally.
    for (int b = gwarp; b < B_TOTAL; b += nwarps) {
        const float4* __restrict__ row =
            reinterpret_cast<const float4*>(inputs + (size_t)b * ROW_FLOATS);

        float acc = 0.0f;
        #pragma unroll
        for (int k = 0; k < VEC_PER_LANE; ++k) {
            const int idx = lane + 32 * k;
            float4 v = __ldcs(&row[idx]);   // evict-first: stream-once data
            float4 c = sc[idx];             // conflict-free LDS.128
            acc += v.x * c.x;
            acc += v.y * c.y;
            acc += v.z * c.z;
            acc += v.w * c.w;
        }

        // Warp butterfly reduce
        #pragma unroll
        for (int off = 16; off > 0; off >>= 1) {
            acc += __shfl_xor_sync(0xFFFFFFFFu, acc, off);
        }

        if (lane == 0) {
            out[b] = acc * INV_NUM_BINS;
        }
    }
}

extern "C" void kernel_launch(void* const* d_in, const int* in_sizes, int n_in,
                              void* d_out, int out_size)
{
    const float* inputs    = (const float*)d_in[0];   // [32768, 16, 128] f32
    const float* centroids = (const float*)d_in[1];   // [16, 128] f32
    float* out             = (float*)d_out;           // [32768] f32

    bins_combiner_kernel<<<GRID_BLOCKS, THREADS>>>(inputs, centroids, out);
}